// round 6
// baseline (speedup 1.0000x reference)
#include <cuda_runtime.h>
#include <math.h>
#include <stdint.h>

// Shapes: T_FAST=512, T_SLOW=128, B=32, D=1024, H=256
// Inputs: 0..3 feat[T,B,D] f32; 4 mlp_w1[16,2048,256]; 5 mlp_b1[16,256];
// 6 mlp_w2[16,256,1]; 7 mlp_b2[16,1]; 8 s2f_w[1024,1024,1]; 9 s2f_b[1024];
// 10 f2s_w[4,1024,1024,5]
// Output: concat(out0[512,32,1024], out1, out2[128,32,1024], out3) f32

#define BATCH 32
#define DDIM  1024

// ---------------- scratch ----------------
static __device__ float g_means[4][BATCH][DDIM];
static __device__ float g_score[16][BATCH];
static __device__ float g_selscore[4][BATCH];
static __device__ int   g_sel[4];
static __device__ __align__(128) float g_y[2][128 * BATCH * DDIM];   // s2f out, 33.5 MB
static __device__ __align__(128) float g_wB[2][1024 * 5120];         // f2s W fragment-packed, 42 MB
static __device__ __align__(128) float g_wS[1024 * 1024];            // s2f W fragment-packed, 4 MB

__constant__ int c_api[8] = {2, 2, 3, 3, 0, 0, 1, 1};
__constant__ int c_apj[8] = {0, 1, 0, 1, 2, 3, 2, 3};

// ---------------- helpers ----------------
__device__ __forceinline__ float to_tf32(float x) {
    uint32_t u; asm("cvt.rna.tf32.f32 %0, %1;" : "=r"(u) : "f"(x));
    return __uint_as_float(u);
}
__device__ __forceinline__ uint32_t smem_u32(const void* p) {
    return (uint32_t)__cvta_generic_to_shared(p);
}
__device__ __forceinline__ void cp16(uint32_t dst, const void* src, int sz) {
    asm volatile("cp.async.ca.shared.global [%0], [%1], 16, %2;" :: "r"(dst), "l"(src), "r"(sz));
}
__device__ __forceinline__ void cp_commit() { asm volatile("cp.async.commit_group;"); }
template <int N> __device__ __forceinline__ void cp_wait() {
    asm volatile("cp.async.wait_group %0;" :: "n"(N));
}
__device__ __forceinline__ void mma_tf32(float (&c)[4], uint32_t a0, uint32_t a1, uint32_t a2,
                                         uint32_t a3, uint32_t b0, uint32_t b1) {
    asm("mma.sync.aligned.m16n8k8.row.col.f32.tf32.tf32.f32 "
        "{%0,%1,%2,%3},{%4,%5,%6,%7},{%8,%9},{%0,%1,%2,%3};"
        : "+f"(c[0]), "+f"(c[1]), "+f"(c[2]), "+f"(c[3])
        : "r"(a0), "r"(a1), "r"(a2), "r"(a3), "r"(b0), "r"(b1));
}
#define LDSM4(r, a) \
    asm volatile("ldmatrix.sync.aligned.m8n8.x4.shared.b16 {%0,%1,%2,%3}, [%4];" \
        : "=r"((r)[0]), "=r"((r)[1]), "=r"((r)[2]), "=r"((r)[3]) : "r"(a))
#define LDS128(r, a) \
    asm volatile("ld.shared.v4.b32 {%0,%1,%2,%3}, [%4];" \
        : "=r"((r)[0]), "=r"((r)[1]), "=r"((r)[2]), "=r"((r)[3]) : "r"(a))

// GEMM tiling: CTA = 128 n x 256 dout, BK = 16, 512 threads (warps: wm=wid&3 n, wn=wid>>2 d)
// A smem: [128 rows][20 floats] (16 used, pad 4) per stage = 10240 B
// B smem: fragment-packed 4096 floats per stage = 16384 B
// B pack order within a 16k x 256d K-tile chunk (4096 floats):
//   [ks(2)][kh(2)][wn(4)][grp(8)][tg(4)][niq(2)][n4(4)]
//   value = W[dout = wn*64 + (niq*4+n4)*8 + grp][k = ks*8 + kh*4 + tg]
#define ASTAGE 10240
#define BSTAGE 16384
#define GSMEM  (3 * (ASTAGE + BSTAGE))

// ---------------- 1) means ----------------
__global__ void means_kernel(const float* __restrict__ f0, const float* __restrict__ f1,
                             const float* __restrict__ f2, const float* __restrict__ f3) {
    int z = blockIdx.y;
    const float* f = (z == 0) ? f0 : (z == 1) ? f1 : (z == 2) ? f2 : f3;
    int T = (z < 2) ? 512 : 128;
    int idx = blockIdx.x * blockDim.x + threadIdx.x;
    if (idx >= BATCH * DDIM) return;
    float s0 = 0.f, s1 = 0.f, s2 = 0.f, s3 = 0.f;
    const float* p = f + idx;
    const int STRIDE = BATCH * DDIM;
    #pragma unroll 4
    for (int t = 0; t < T; t += 4) {
        s0 += p[(size_t)(t + 0) * STRIDE];
        s1 += p[(size_t)(t + 1) * STRIDE];
        s2 += p[(size_t)(t + 2) * STRIDE];
        s3 += p[(size_t)(t + 3) * STRIDE];
    }
    (&g_means[z][0][0])[idx] = ((s0 + s1) + (s2 + s3)) * (1.0f / (float)T);
}

// ---------------- 2) pair-gate MLPs ----------------
__global__ void mlp_kernel(const float* __restrict__ w1, const float* __restrict__ b1,
                           const float* __restrict__ w2, const float* __restrict__ b2) {
    __shared__ float vec[4][2048];
    __shared__ float red[4][256];
    int pi = blockIdx.x, bg = blockIdx.y;
    int i = c_api[pi], j = c_apj[pi];
    int p = i * 4 + j;
    int tid = threadIdx.x;
    for (int q = 0; q < 4; ++q) {
        int b = bg * 4 + q;
        for (int k = tid; k < 2048; k += 256)
            vec[q][k] = (k < 1024) ? g_means[i][b][k] : g_means[j][b][k - 1024];
    }
    __syncthreads();
    const float* w1p = w1 + (size_t)p * 2048 * 256 + tid;
    float a0 = 0.f, a1 = 0.f, a2 = 0.f, a3 = 0.f;
    #pragma unroll 4
    for (int k = 0; k < 2048; ++k) {
        float w = w1p[(size_t)k * 256];
        a0 = fmaf(vec[0][k], w, a0);
        a1 = fmaf(vec[1][k], w, a1);
        a2 = fmaf(vec[2][k], w, a2);
        a3 = fmaf(vec[3][k], w, a3);
    }
    float bb = b1[p * 256 + tid];
    float wv = w2[p * 256 + tid];
    red[0][tid] = fmaxf(a0 + bb, 0.f) * wv;
    red[1][tid] = fmaxf(a1 + bb, 0.f) * wv;
    red[2][tid] = fmaxf(a2 + bb, 0.f) * wv;
    red[3][tid] = fmaxf(a3 + bb, 0.f) * wv;
    __syncthreads();
    for (int s = 128; s > 0; s >>= 1) {
        if (tid < s) {
            red[0][tid] += red[0][tid + s];
            red[1][tid] += red[1][tid + s];
            red[2][tid] += red[2][tid + s];
            red[3][tid] += red[3][tid + s];
        }
        __syncthreads();
    }
    if (tid < 4) {
        float z = red[tid][0] + b2[p];
        g_score[p][bg * 4 + tid] = 1.f / (1.f + expf(-z));
    }
}

// ---------------- 3) resolve where-chains ----------------
__global__ void select_kernel() {
    int j = threadIdx.x >> 5;
    int lane = threadIdx.x & 31;
    int pA, pB, iA, iB;
    if (j < 2) { pA = 12 + j; iA = 3; pB = 8 + j; iB = 2; }
    else       { pA = 4 + j;  iA = 1; pB = j;     iB = 0; }
    float sA = g_score[pA][lane], sB = g_score[pB][lane];
    float mA = sA, mB = sB;
    #pragma unroll
    for (int o = 16; o > 0; o >>= 1) {
        mA += __shfl_xor_sync(0xffffffffu, mA, o);
        mB += __shfl_xor_sync(0xffffffffu, mB, o);
    }
    bool cA = (mA * (1.f / 32.f)) >= 0.3f;
    bool cB = (mB * (1.f / 32.f)) >= 0.3f;
    int sel = cA ? iA : (cB ? iB : -1);
    g_selscore[j][lane] = cA ? sA : (cB ? sB : 0.f);
    if (lane == 0) g_sel[j] = sel;
}

// ---------------- 4) repack weights into fragment-packed tf32 layout ----------------
// f2s: g_wB[slot] laid as [dt(4)][kt(320)][4096-frag-chunk]
// s2f: g_wS       laid as [dt(4)][kt(64)][4096-frag-chunk]
__global__ void repack_kernel(const float* __restrict__ f2s_w, const float* __restrict__ s2f_w) {
    long long idx = (long long)blockIdx.x * blockDim.x + threadIdx.x;
    const long long per_slot = 5LL * 1024 * 1024;      // 5242880
    if (idx < 2 * per_slot) {
        int slot = (int)(idx / per_slot);
        int sel = g_sel[slot + 2];
        if (sel < 0) return;
        int widx = sel * 2 + slot;
        long long r = idx - (long long)slot * per_slot;
        int dt = (int)(r / (320 * 4096));
        int r2 = (int)(r % (320 * 4096));
        int kt = r2 >> 12, q = r2 & 4095;
        int ks = q >> 11, kh = (q >> 10) & 1, wn = (q >> 8) & 3;
        int grp = (q >> 5) & 7, tg = (q >> 3) & 3, niq = (q >> 2) & 1, n4 = q & 3;
        int dout = dt * 256 + wn * 64 + (niq * 4 + n4) * 8 + grp;
        int k = kt * 16 + ks * 8 + kh * 4 + tg;
        int tap = k >> 10, din = k & 1023;
        g_wB[slot][r] = to_tf32(f2s_w[(((long long)widx * 1024 + dout) * 1024 + din) * 5 + tap]);
    } else {
        long long r = idx - 2 * per_slot;
        if (r >= 1024 * 1024) return;
        if (g_sel[0] < 0 && g_sel[1] < 0) return;
        int dt = (int)(r >> 18);
        int r2 = (int)(r & 262143);
        int kt = r2 >> 12, q = r2 & 4095;
        int ks = q >> 11, kh = (q >> 10) & 1, wn = (q >> 8) & 3;
        int grp = (q >> 5) & 7, tg = (q >> 3) & 3, niq = (q >> 2) & 1, n4 = q & 3;
        int dout = dt * 256 + wn * 64 + (niq * 4 + n4) * 8 + grp;
        int k = kt * 16 + ks * 8 + kh * 4 + tg;
        g_wS[r] = to_tf32(s2f_w[(size_t)dout * 1024 + k]);
    }
}

// ---------------- shared GEMM compute for one 16-K stage ----------------
__device__ __forceinline__ void gemm_stage(uint32_t a_lm, uint32_t b_base, float (&acc)[2][8][4]) {
    #pragma unroll
    for (int ks = 0; ks < 2; ++ks) {
        uint32_t A0[4], A1[4];
        LDSM4(A0, a_lm + ks * 32);                 // mi=0: rows wm*32..+15
        LDSM4(A1, a_lm + 1280 + ks * 32);          // mi=1: +16 rows (16*20*4 bytes)
        uint32_t bf00[4], bf01[4], bf10[4], bf11[4];
        uint32_t bb = b_base + ks * 8192;
        LDS128(bf00, bb);                          // kh0 niq0 -> b0 of ni 0..3
        LDS128(bf01, bb + 16);                     // kh0 niq1 -> b0 of ni 4..7
        LDS128(bf10, bb + 4096);                   // kh1 niq0 -> b1 of ni 0..3
        LDS128(bf11, bb + 4096 + 16);              // kh1 niq1 -> b1 of ni 4..7
        #pragma unroll
        for (int ni = 0; ni < 4; ++ni) {
            mma_tf32(acc[0][ni], A0[0], A0[1], A0[2], A0[3], bf00[ni], bf10[ni]);
            mma_tf32(acc[1][ni], A1[0], A1[1], A1[2], A1[3], bf00[ni], bf10[ni]);
            mma_tf32(acc[0][ni + 4], A0[0], A0[1], A0[2], A0[3], bf01[ni], bf11[ni]);
            mma_tf32(acc[1][ni + 4], A1[0], A1[1], A1[2], A1[3], bf01[ni], bf11[ni]);
        }
    }
}

// ---------------- 5) s2f GEMM: y[n,dout] = X[n,:] . W[dout,:] + b ----------------
__global__ __launch_bounds__(512, 1)
void s2f_mma(const float* __restrict__ f2, const float* __restrict__ f3,
             const float* __restrict__ bias) {
    int slot = blockIdx.z;
    int sel = g_sel[slot];
    if (sel < 0) return;
    const float* X = (sel == 3) ? f3 : f2;
    float* Y = g_y[slot];
    int n0 = blockIdx.x * 128, dt = blockIdx.y;
    int tid = threadIdx.x, wid = tid >> 5, lane = tid & 31;
    int wm = wid & 3, wn = wid >> 2;
    int grp = lane >> 2, tg = lane & 3;
    int q = lane >> 3, rr = lane & 7;
    extern __shared__ __align__(16) float dsm[];
    uint32_t sbA = smem_u32(dsm);
    uint32_t sbB = sbA + 3 * ASTAGE;
    float acc[2][8][4];
    #pragma unroll
    for (int a = 0; a < 2; ++a)
        #pragma unroll
        for (int b = 0; b < 8; ++b)
            #pragma unroll
            for (int c = 0; c < 4; ++c) acc[a][b][c] = 0.f;

    int arow = tid >> 2, ac = tid & 3;
    const float* asrc0 = X + (size_t)(n0 + arow) * 1024 + ac * 4;
    uint32_t adst = sbA + (uint32_t)(arow * 20 + ac * 4) * 4;
    const float* bsrc0 = g_wS + (size_t)dt * (64 * 4096);
    uint32_t a_lm = sbA + (uint32_t)((wm * 32 + (q & 1) * 8 + rr) * 20 + (q >> 1) * 4) * 4;
    uint32_t b_base = sbB + (uint32_t)(wn * 256 + grp * 32 + tg * 8) * 4;
    const int KT = 64;

    #define S2F_LD(kt, st) do { \
        cp16(adst + (st) * ASTAGE, asrc0 + (kt) * 16, 16); \
        const float* b_ = bsrc0 + (size_t)(kt) * 4096; \
        uint32_t bd_ = sbB + (st) * BSTAGE + tid * 16; \
        cp16(bd_, b_ + tid * 4, 16); \
        cp16(bd_ + 8192, b_ + tid * 4 + 2048, 16); \
        cp_commit(); \
    } while (0)

    S2F_LD(0, 0); S2F_LD(1, 1);
    for (int kt = 0; kt < KT; ++kt) {
        int s = kt % 3;
        if (kt + 1 < KT) cp_wait<1>(); else cp_wait<0>();
        __syncthreads();
        if (kt + 2 < KT) { int s2 = (kt + 2) % 3; S2F_LD(kt + 2, s2); }
        gemm_stage(a_lm + s * ASTAGE, b_base + s * BSTAGE, acc);
    }
    // epilogue
    int rbase = n0 + wm * 32 + grp;
    int cbase = dt * 256 + wn * 64 + 2 * tg;
    #pragma unroll
    for (int mi = 0; mi < 2; ++mi) {
        int r1 = rbase + mi * 16, r2 = r1 + 8;
        #pragma unroll
        for (int ni = 0; ni < 8; ++ni) {
            int c = cbase + ni * 8;
            float bz0 = bias[c], bz1 = bias[c + 1];
            *(float2*)(Y + (size_t)r1 * 1024 + c) = make_float2(acc[mi][ni][0] + bz0, acc[mi][ni][1] + bz1);
            *(float2*)(Y + (size_t)r2 * 1024 + c) = make_float2(acc[mi][ni][2] + bz0, acc[mi][ni][3] + bz1);
        }
    }
    #undef S2F_LD
}

// ---------------- 6) fast outputs: upsample + gated residual ----------------
__global__ void upsample_kernel(const float* __restrict__ f0, const float* __restrict__ f1,
                                float* __restrict__ out) {
    int slot = blockIdx.y;
    const float* FJ = slot ? f1 : f0;
    float* O = out + (size_t)slot * 16777216;
    int idx4 = blockIdx.x * blockDim.x + threadIdx.x;
    if (idx4 >= 512 * 32 * 256) return;
    float4 base = ((const float4*)FJ)[idx4];
    float4 res = base;
    int sel = g_sel[slot];
    if (sel >= 0) {
        int t = idx4 / (32 * 256);
        int rem = idx4 % (32 * 256);
        int b = rem >> 8;
        float s = g_selscore[slot][b];
        float srcp = (t + 0.5f) * 0.25f - 0.5f;
        srcp = fminf(fmaxf(srcp, 0.f), 127.f);
        int i0 = (int)floorf(srcp);
        int i1 = min(i0 + 1, 127);
        float wgt = srcp - (float)i0;
        const float4* yp = (const float4*)g_y[slot];
        float4 a = yp[i0 * (32 * 256) + rem];
        float4 c = yp[i1 * (32 * 256) + rem];
        res.x = base.x + s * ((1.f - wgt) * a.x + wgt * c.x);
        res.y = base.y + s * ((1.f - wgt) * a.y + wgt * c.y);
        res.z = base.z + s * ((1.f - wgt) * a.z + wgt * c.z);
        res.w = base.w + s * ((1.f - wgt) * a.w + wgt * c.w);
    }
    ((float4*)O)[idx4] = res;
}

// ---------------- 7) f2s GEMM + gated residual ----------------
__global__ __launch_bounds__(512, 1)
void f2s_mma(const float* __restrict__ f0, const float* __restrict__ f1,
             const float* __restrict__ f2, const float* __restrict__ f3,
             float* __restrict__ outbase) {
    int slot = blockIdx.z, j = slot + 2;
    const float* FJ = slot ? f3 : f2;
    float* O = outbase + (slot ? (size_t)37748736 : (size_t)33554432);
    int n0 = blockIdx.x * 128, dt = blockIdx.y;
    int tid = threadIdx.x;
    int sel = g_sel[j];
    if (sel < 0) {                       // pass-through copy of this tile
        for (int i = tid; i < 128 * 64; i += 512) {
            int r = i >> 6, c4 = i & 63;
            size_t off = (size_t)(n0 + r) * 1024 + dt * 256 + c4 * 4;
            *(float4*)(O + off) = *(const float4*)(FJ + off);
        }
        return;
    }
    const float* X = (sel == 1) ? f1 : f0;   // [512][32][1024]
    int wid = tid >> 5, lane = tid & 31;
    int wm = wid & 3, wn = wid >> 2;
    int grp = lane >> 2, tg = lane & 3;
    int q = lane >> 3, rr = lane & 7;
    extern __shared__ __align__(16) float dsm[];
    uint32_t sbA = smem_u32(dsm);
    uint32_t sbB = sbA + 3 * ASTAGE;
    float acc[2][8][4];
    #pragma unroll
    for (int a = 0; a < 2; ++a)
        #pragma unroll
        for (int b = 0; b < 8; ++b)
            #pragma unroll
            for (int c = 0; c < 4; ++c) acc[a][b][c] = 0.f;

    int arow = tid >> 2, ac = tid & 3;
    int nA = n0 + arow, tL = nA >> 5, bA = nA & 31;
    const float* asrc0 = X + (size_t)bA * 1024 + ac * 4;
    uint32_t adst = sbA + (uint32_t)(arow * 20 + ac * 4) * 4;
    const float* bsrc0 = g_wB[slot] + (size_t)dt * (320 * 4096);
    uint32_t a_lm = sbA + (uint32_t)((wm * 32 + (q & 1) * 8 + rr) * 20 + (q >> 1) * 4) * 4;
    uint32_t b_base = sbB + (uint32_t)(wn * 256 + grp * 32 + tg * 8) * 4;
    const int KT = 320;

    #define F2S_LD(kt, st) do { \
        int tap_ = (kt) >> 6, din0_ = ((kt) & 63) << 4; \
        int time_ = 4 * tL - 2 + tap_; \
        const float* a_ = asrc0 + (size_t)time_ * 32768 + din0_; \
        cp16(adst + (st) * ASTAGE, (time_ >= 0) ? a_ : (const float*)X, (time_ >= 0) ? 16 : 0); \
        const float* b_ = bsrc0 + (size_t)(kt) * 4096; \
        uint32_t bd_ = sbB + (st) * BSTAGE + tid * 16; \
        cp16(bd_, b_ + tid * 4, 16); \
        cp16(bd_ + 8192, b_ + tid * 4 + 2048, 16); \
        cp_commit(); \
    } while (0)

    F2S_LD(0, 0); F2S_LD(1, 1);
    for (int kt = 0; kt < KT; ++kt) {
        int s = kt % 3;
        if (kt + 1 < KT) cp_wait<1>(); else cp_wait<0>();
        __syncthreads();
        if (kt + 2 < KT) { int s2 = (kt + 2) % 3; F2S_LD(kt + 2, s2); }
        gemm_stage(a_lm + s * ASTAGE, b_base + s * BSTAGE, acc);
    }
    // epilogue: O = FJ + score[b] * acc
    int rbase = n0 + wm * 32 + grp;
    int cbase = dt * 256 + wn * 64 + 2 * tg;
    #pragma unroll
    for (int mi = 0; mi < 2; ++mi) {
        int r1 = rbase + mi * 16, r2 = r1 + 8;
        float s1 = g_selscore[j][r1 & 31];
        float s2v = g_selscore[j][r2 & 31];
        #pragma unroll
        for (int ni = 0; ni < 8; ++ni) {
            int c = cbase + ni * 8;
            float2 b1 = *(const float2*)(FJ + (size_t)r1 * 1024 + c);
            float2 b2 = *(const float2*)(FJ + (size_t)r2 * 1024 + c);
            *(float2*)(O + (size_t)r1 * 1024 + c) =
                make_float2(b1.x + s1 * acc[mi][ni][0], b1.y + s1 * acc[mi][ni][1]);
            *(float2*)(O + (size_t)r2 * 1024 + c) =
                make_float2(b2.x + s2v * acc[mi][ni][2], b2.y + s2v * acc[mi][ni][3]);
        }
    }
    #undef F2S_LD
}

// ---------------- launch ----------------
extern "C" void kernel_launch(void* const* d_in, const int* in_sizes, int n_in,
                              void* d_out, int out_size) {
    (void)in_sizes; (void)n_in; (void)out_size;
    const float* f0 = (const float*)d_in[0];
    const float* f1 = (const float*)d_in[1];
    const float* f2 = (const float*)d_in[2];
    const float* f3 = (const float*)d_in[3];
    const float* w1 = (const float*)d_in[4];
    const float* b1 = (const float*)d_in[5];
    const float* w2 = (const float*)d_in[6];
    const float* b2 = (const float*)d_in[7];
    const float* s2f_w = (const float*)d_in[8];
    const float* s2f_b = (const float*)d_in[9];
    const float* f2s_w = (const float*)d_in[10];
    float* out = (float*)d_out;

    cudaFuncSetAttribute(s2f_mma, cudaFuncAttributeMaxDynamicSharedMemorySize, GSMEM);
    cudaFuncSetAttribute(f2s_mma, cudaFuncAttributeMaxDynamicSharedMemorySize, GSMEM);

    means_kernel<<<dim3(128, 4), 256>>>(f0, f1, f2, f3);
    mlp_kernel<<<dim3(8, 8), 256>>>(w1, b1, w2, b2);
    select_kernel<<<1, 128>>>();
    repack_kernel<<<45056, 256>>>(f2s_w, s2f_w);
    s2f_mma<<<dim3(32, 4, 2), 512, GSMEM>>>(f2, f3, s2f_b);
    upsample_kernel<<<dim3(16384, 2), 256>>>(f0, f1, out);
    f2s_mma<<<dim3(32, 4, 2), 512, GSMEM>>>(f0, f1, f2, f3, out);
}